// round 15
// baseline (speedup 1.0000x reference)
#include <cuda_runtime.h>
#include <cstdint>

// Neo-Hookean 3D material point: psi, Cauchy (Voigt 6), DDSDDE (6x6) per point.
// Output layout (flattened tuple): [N] psi | [N,6] Cauchy6 | [N,36] DDSDDE.
//
// R15: two tiles per warp inside a one-shot block (no persistent loop).
// Both tiles' F staged up front (F_B latency hidden behind compute A);
// TMA_A committed without wait and covered by compute B; its buffer is then
// reused for ddB. Exposed TMA tail amortized over 64 pts instead of 32.
// Per-warp smem = 4608 (ddA/F_A alias) + 1152 (F_B) = 5760B -> 23KB/block
// -> 10 blocks/SM (40 warps). Cache hints reverted to R9 (.cs) — both L2
// policy experiments regressed.

#define TPB 128
#define ROW 36
#define WARP_DD_FLOATS (32 * ROW)            // 1152 floats = 4608 B
#define WARP_FB_FLOATS (32 * 9)              //  288 floats = 1152 B
#define WARP_REGION    (WARP_DD_FLOATS + WARP_FB_FLOATS)   // 1440 floats
#define SMEM_FLOATS    (4 * WARP_REGION)     // 5760 floats = 23040 B

__device__ __forceinline__ uint32_t smem_u32(const void* p) {
    uint32_t a;
    asm("{ .reg .u64 t; cvta.to.shared.u64 t, %1; cvt.u32.u64 %0, t; }"
        : "=r"(a) : "l"(p));
    return a;
}

__device__ __forceinline__ void nh3d_point(
    const float F[3][3], float c1, float c2,
    float& psi, float cau[6], float dd[36])
{
    // B = F F^T (symmetric)
    float B[3][3];
    #pragma unroll
    for (int i = 0; i < 3; i++)
        #pragma unroll
        for (int j = 0; j < 3; j++)
            B[i][j] = F[i][0]*F[j][0] + F[i][1]*F[j][1] + F[i][2]*F[j][2];

    float J = F[0][0]*(F[1][1]*F[2][2] - F[1][2]*F[2][1])
            - F[0][1]*(F[1][0]*F[2][2] - F[1][2]*F[2][0])
            + F[0][2]*(F[1][0]*F[2][1] - F[1][1]*F[2][0]);

    float I1   = B[0][0] + B[1][1] + B[2][2];
    float Jm23 = 1.0f / cbrtf(J * J);      // J^{-2/3}
    float invJ = 1.0f / J;

    float a = 2.0f * c1 * Jm23;
    float b = 2.0f * c2 * (J - 1.0f) * J;

    // Kirchhoff stress tau = a*(B - I1/3 * I) + b*I
    float tau[3][3];
    #pragma unroll
    for (int i = 0; i < 3; i++)
        #pragma unroll
        for (int j = 0; j < 3; j++)
            tau[i][j] = a * (B[i][j] - (i == j ? I1 * (1.0f/3.0f) : 0.0f))
                      + (i == j ? b : 0.0f);

    psi = c1 * (Jm23 * I1 - 3.0f) + c2 * (J - 1.0f) * (J - 1.0f);

    // Spatial tangent:
    // Stiff_ijkl = c_dd d_ij d_kl + c_bd (B_ij d_kl + d_ij B_kl)
    //            + a d_ik B_jl + c_sw d_il d_jk
    //            + 0.5*(tau_ik d_jl + tau_il d_jk + tau_jk d_il - tau_jl d_ik)
    float c_dd = (2.0f/9.0f) * a * I1 + 2.0f * c2 * (2.0f*J - 1.0f) * J;
    float c_bd = -(2.0f/3.0f) * a;
    float c_sw = a * I1 * (1.0f/3.0f) - b;

    const int II[6] = {0, 1, 2, 0, 0, 1};
    const int JJ[6] = {0, 1, 2, 1, 2, 2};

    #pragma unroll
    for (int r = 0; r < 6; r++)
        cau[r] = tau[II[r]][JJ[r]] * invJ;

    #pragma unroll
    for (int r = 0; r < 6; r++) {
        const int i = II[r], j = JJ[r];
        #pragma unroll
        for (int c = 0; c < 6; c++) {
            const int k = II[c], l = JJ[c];
            float s = 0.0f;
            if (i == j && k == l) s += c_dd;
            if (k == l)           s += c_bd * B[i][j];
            if (i == j)           s += c_bd * B[k][l];
            if (i == k)           s += a * B[j][l];
            if (i == l && j == k) s += c_sw;
            float g = 0.0f;
            if (j == l) g += tau[i][k];
            if (j == k) g += tau[i][l];
            if (i == l) g += tau[j][k];
            if (i == k) g -= tau[j][l];
            s += 0.5f * g;
            dd[r*6 + c] = s * invJ;
        }
    }
}

// stage one warp-tile's F (1152B contiguous) into smem via LDG.128/STS.128
__device__ __forceinline__ void stage_F(float* buf, const float* F_in,
                                        int pt0, int lane) {
    const float4* g4 = reinterpret_cast<const float4*>(F_in + (size_t)pt0 * 9);
    float4* s4 = reinterpret_cast<float4*>(buf);
    s4[lane]      = __ldcs(g4 + lane);
    s4[lane + 32] = __ldcs(g4 + lane + 32);
    if (lane < 8) s4[lane + 64] = __ldcs(g4 + lane + 64);
}

// direct psi + cau streaming stores for one point
__device__ __forceinline__ void store_psi_cau(float* out, int n, int p,
                                              float psi, const float cau[6]) {
    __stcs(out + p, psi);
    float2* c2p = reinterpret_cast<float2*>(out + (size_t)n + (size_t)p * 6);
    __stcs(c2p + 0, make_float2(cau[0], cau[1]));
    __stcs(c2p + 1, make_float2(cau[2], cau[3]));
    __stcs(c2p + 2, make_float2(cau[4], cau[5]));
}

// stage this lane's dd row (144B) into the warp dd buffer
__device__ __forceinline__ void stage_dd(float* ddbuf, int lane, const float dd[36]) {
    float4* row4 = reinterpret_cast<float4*>(ddbuf + lane * ROW);
    #pragma unroll
    for (int q = 0; q < 9; q++)
        row4[q] = make_float4(dd[4*q+0], dd[4*q+1], dd[4*q+2], dd[4*q+3]);
}

// scalar fallback for one lane's point
__device__ __forceinline__ void scalar_point(const float* F_in, float* out,
                                             int n, int p, float c1, float c2) {
    if (p >= n) return;
    float F[3][3], psi, cau[6], dd[36];
    const float* Fp = F_in + (size_t)p * 9;
    #pragma unroll
    for (int i = 0; i < 9; i++)
        (&F[0][0])[i] = __ldcs(Fp + i);
    nh3d_point(F, c1, c2, psi, cau, dd);
    __stcs(out + p, psi);
    float* cbase = out + (size_t)n + (size_t)p * 6;
    #pragma unroll
    for (int q = 0; q < 6; q++) __stcs(cbase + q, cau[q]);
    float* dbase = out + (size_t)n * 7 + (size_t)p * 36;
    #pragma unroll
    for (int q = 0; q < 36; q++) __stcs(dbase + q, dd[q]);
}

__global__ __launch_bounds__(TPB, 10) void nh3d_kernel(
    const float* __restrict__ F_in,
    const float* __restrict__ mat_par,
    float* __restrict__ out,
    int n, int vec_ok)
{
    __shared__ __align__(16) float sbuf[SMEM_FLOATS];   // 23040 B

    const int tid  = threadIdx.x;
    const int wid  = tid >> 5;
    const int lane = tid & 31;
    const int bs   = blockIdx.x * (TPB * 2);            // 256 points per block
    const float c1 = mat_par[0];
    const float c2 = mat_par[1];

    float* reg   = sbuf + wid * WARP_REGION;
    float* bufA  = reg;                     // 1152 floats: F_A then ddA then ddB
    float* bufFB = reg + WARP_DD_FLOATS;    //  288 floats: F_B

    const int ptA = bs + wid * 32;
    const int ptB = bs + TPB + wid * 32;
    const bool fastA = vec_ok && (ptA + 32 <= n);
    const bool fastB = vec_ok && (ptB + 32 <= n);

    float F[3][3], psi, cau[6], dd[36];

    // ---- stage both tiles' F up front: F_B latency hides behind compute A ----
    if (fastA) stage_F(bufA,  F_in, ptA, lane);
    if (fastB) stage_F(bufFB, F_in, ptB, lane);
    __syncwarp();

    // ================= tile A =================
    if (fastA) {
        const float* myF = bufA + lane * 9;        // stride 9: conflict-free
        #pragma unroll
        for (int i = 0; i < 9; i++) (&F[0][0])[i] = myF[i];
        __syncwarp();                               // F_A consumed -> bufA reusable

        nh3d_point(F, c1, c2, psi, cau, dd);
        store_psi_cau(out, n, ptA + lane, psi, cau);

        stage_dd(bufA, lane, dd);
        __syncwarp();
        if (lane == 0) {
            asm volatile("fence.proxy.async.shared::cta;" ::: "memory");
            float* ddst = out + (size_t)n * 7 + (size_t)ptA * 36;
            asm volatile(
                "cp.async.bulk.global.shared::cta.bulk_group [%0], [%1], %2;"
                :: "l"(ddst), "r"(smem_u32(bufA)), "n"(WARP_DD_FLOATS * 4) : "memory");
            asm volatile("cp.async.bulk.commit_group;" ::: "memory");
            // NO wait here: TMA_A flies under compute B
        }
    } else {
        scalar_point(F_in, out, n, ptA + lane, c1, c2);
    }

    // ================= tile B =================
    if (fastB) {
        const float* myF = bufFB + lane * 9;
        #pragma unroll
        for (int i = 0; i < 9; i++) (&F[0][0])[i] = myF[i];

        nh3d_point(F, c1, c2, psi, cau, dd);
        store_psi_cau(out, n, ptB + lane, psi, cau);

        // retire TMA_A (had all of compute B to finish) before reusing bufA
        if (lane == 0)
            asm volatile("cp.async.bulk.wait_group 0;" ::: "memory");
        __syncwarp();

        stage_dd(bufA, lane, dd);
        __syncwarp();
        if (lane == 0) {
            asm volatile("fence.proxy.async.shared::cta;" ::: "memory");
            float* ddst = out + (size_t)n * 7 + (size_t)ptB * 36;
            asm volatile(
                "cp.async.bulk.global.shared::cta.bulk_group [%0], [%1], %2;"
                :: "l"(ddst), "r"(smem_u32(bufA)), "n"(WARP_DD_FLOATS * 4) : "memory");
            asm volatile("cp.async.bulk.commit_group;" ::: "memory");
        }
    } else if (ptB + lane < n) {
        scalar_point(F_in, out, n, ptB + lane, c1, c2);
    }

    // final: smem must stay valid until this warp's last TMA completes
    if (lane == 0)
        asm volatile("cp.async.bulk.wait_group 0;" ::: "memory");
}

extern "C" void kernel_launch(void* const* d_in, const int* in_sizes, int n_in,
                              void* d_out, int out_size) {
    const float* F_in    = (const float*)d_in[0];
    const float* mat_par = (const float*)d_in[1];
    float* out = (float*)d_out;
    int n = in_sizes[0] / 9;

    // fast path: dd bulk dst (7n floats, 4608B warp chunks) needs 16B,
    // cau float2 needs 8B -> n % 4 == 0.
    int vec_ok = ((n % 4) == 0) ? 1 : 0;

    int pts_per_block = TPB * 2;
    int blocks = (n + pts_per_block - 1) / pts_per_block;
    nh3d_kernel<<<blocks, TPB>>>(F_in, mat_par, out, n, vec_ok);
}

// round 16
// speedup vs baseline: 1.0584x; 1.0584x over previous
#include <cuda_runtime.h>
#include <cstdint>

// Neo-Hookean 3D material point: psi, Cauchy (Voigt 6), DDSDDE (6x6) per point.
// Output layout (flattened tuple): [N] psi | [N,6] Cauchy6 | [N,36] DDSDDE.
//
// R16 = R9 (champion: TPB=128, warp-local staging, per-warp bulk-TMA dd
// drain, separate F/dd buffers, .cs scalar stores) with ONE reorder: the
// psi/cau direct stores are issued AFTER the TMA commit, so they execute
// under the TMA flight and the terminal wait_group has less exposed time.
// All other structures (persistence, 2-tile pipelines, L2 policies, block
// resizing) measured neutral-to-worse across R4-R15; steady-state traffic
// (212MB/replay at ~6.0 TB/s) says we are at the HBM wall.

#define TPB 128
#define ROW 36
#define WARPS_PER_BLOCK (TPB / 32)
#define WARP_F_FLOATS  (32 * 9)             // 1152 B per warp
#define WARP_DD_FLOATS (32 * ROW)           // 4608 B per warp
#define DD_SMEM_FLOATS (TPB * ROW)          // 18432 B
#define F_SMEM_FLOATS  (TPB * 9)            //  4608 B

__device__ __forceinline__ uint32_t smem_u32(const void* p) {
    uint32_t a;
    asm("{ .reg .u64 t; cvta.to.shared.u64 t, %1; cvt.u32.u64 %0, t; }"
        : "=r"(a) : "l"(p));
    return a;
}

__device__ __forceinline__ void nh3d_point(
    const float F[3][3], float c1, float c2,
    float& psi, float cau[6], float dd[36])
{
    // B = F F^T (symmetric)
    float B[3][3];
    #pragma unroll
    for (int i = 0; i < 3; i++)
        #pragma unroll
        for (int j = 0; j < 3; j++)
            B[i][j] = F[i][0]*F[j][0] + F[i][1]*F[j][1] + F[i][2]*F[j][2];

    float J = F[0][0]*(F[1][1]*F[2][2] - F[1][2]*F[2][1])
            - F[0][1]*(F[1][0]*F[2][2] - F[1][2]*F[2][0])
            + F[0][2]*(F[1][0]*F[2][1] - F[1][1]*F[2][0]);

    float I1   = B[0][0] + B[1][1] + B[2][2];
    float Jm23 = 1.0f / cbrtf(J * J);      // J^{-2/3}
    float invJ = 1.0f / J;

    float a = 2.0f * c1 * Jm23;
    float b = 2.0f * c2 * (J - 1.0f) * J;

    // Kirchhoff stress tau = a*(B - I1/3 * I) + b*I
    float tau[3][3];
    #pragma unroll
    for (int i = 0; i < 3; i++)
        #pragma unroll
        for (int j = 0; j < 3; j++)
            tau[i][j] = a * (B[i][j] - (i == j ? I1 * (1.0f/3.0f) : 0.0f))
                      + (i == j ? b : 0.0f);

    psi = c1 * (Jm23 * I1 - 3.0f) + c2 * (J - 1.0f) * (J - 1.0f);

    // Spatial tangent:
    // Stiff_ijkl = c_dd d_ij d_kl + c_bd (B_ij d_kl + d_ij B_kl)
    //            + a d_ik B_jl + c_sw d_il d_jk
    //            + 0.5*(tau_ik d_jl + tau_il d_jk + tau_jk d_il - tau_jl d_ik)
    float c_dd = (2.0f/9.0f) * a * I1 + 2.0f * c2 * (2.0f*J - 1.0f) * J;
    float c_bd = -(2.0f/3.0f) * a;
    float c_sw = a * I1 * (1.0f/3.0f) - b;

    const int II[6] = {0, 1, 2, 0, 0, 1};
    const int JJ[6] = {0, 1, 2, 1, 2, 2};

    #pragma unroll
    for (int r = 0; r < 6; r++)
        cau[r] = tau[II[r]][JJ[r]] * invJ;

    #pragma unroll
    for (int r = 0; r < 6; r++) {
        const int i = II[r], j = JJ[r];
        #pragma unroll
        for (int c = 0; c < 6; c++) {
            const int k = II[c], l = JJ[c];
            float s = 0.0f;
            if (i == j && k == l) s += c_dd;
            if (k == l)           s += c_bd * B[i][j];
            if (i == j)           s += c_bd * B[k][l];
            if (i == k)           s += a * B[j][l];
            if (i == l && j == k) s += c_sw;
            float g = 0.0f;
            if (j == l) g += tau[i][k];
            if (j == k) g += tau[i][l];
            if (i == l) g += tau[j][k];
            if (i == k) g -= tau[j][l];
            s += 0.5f * g;
            dd[r*6 + c] = s * invJ;
        }
    }
}

__global__ __launch_bounds__(TPB, 9) void nh3d_kernel(
    const float* __restrict__ F_in,
    const float* __restrict__ mat_par,
    float* __restrict__ out,
    int n, int vec_ok)
{
    __shared__ __align__(16) float sdd[DD_SMEM_FLOATS];  // 18432 B
    __shared__ __align__(16) float sf[F_SMEM_FLOATS];    //  4608 B

    const int tid  = threadIdx.x;
    const int wid  = tid >> 5;
    const int lane = tid & 31;
    const int block_start = blockIdx.x * TPB;
    const float c1 = mat_par[0];
    const float c2 = mat_par[1];

    float F[3][3];
    float psi, cau[6], dd[36];

    if (vec_ok && block_start + TPB <= n) {
        const int warp_pt0 = block_start + wid * 32;   // first point of this warp

        // ---- warp-local F staging: 72 float4 (1152B contiguous) per warp ----
        {
            const float4* g4 = reinterpret_cast<const float4*>(F_in + (size_t)warp_pt0 * 9);
            float4* s4 = reinterpret_cast<float4*>(sf + wid * WARP_F_FLOATS);
            s4[lane]      = __ldcs(g4 + lane);
            s4[lane + 32] = __ldcs(g4 + lane + 32);
            if (lane < 8) s4[lane + 64] = __ldcs(g4 + lane + 64);
        }
        __syncwarp();
        {
            const float* myF = sf + wid * WARP_F_FLOATS + lane * 9;  // stride 9: conflict-free
            #pragma unroll
            for (int i = 0; i < 9; i++)
                (&F[0][0])[i] = myF[i];
        }

        nh3d_point(F, c1, c2, psi, cau, dd);

        // ---- stage dd FIRST: lane row 144B, warp chunk 4608B contiguous ----
        {
            float4* row4 = reinterpret_cast<float4*>(sdd + wid * WARP_DD_FLOATS + lane * ROW);
            #pragma unroll
            for (int q = 0; q < 9; q++)
                row4[q] = make_float4(dd[4*q+0], dd[4*q+1], dd[4*q+2], dd[4*q+3]);
        }
        __syncwarp();

        // ---- commit the warp's bulk drain immediately (no wait yet) ----
        if (lane == 0) {
            asm volatile("fence.proxy.async.shared::cta;" ::: "memory");
            float* ddst = out + (size_t)n * 7 + (size_t)warp_pt0 * 36;
            uint32_t src = smem_u32(sdd + wid * WARP_DD_FLOATS);
            asm volatile(
                "cp.async.bulk.global.shared::cta.bulk_group [%0], [%1], %2;"
                :: "l"(ddst), "r"(src), "n"(WARP_DD_FLOATS * 4) : "memory");
            asm volatile("cp.async.bulk.commit_group;" ::: "memory");
        }

        // ---- psi + cau direct stores now OVERLAP the TMA flight ----
        {
            const int p = warp_pt0 + lane;
            __stcs(out + p, psi);
            float2* c2p = reinterpret_cast<float2*>(out + (size_t)n + (size_t)p * 6);
            __stcs(c2p + 0, make_float2(cau[0], cau[1]));
            __stcs(c2p + 1, make_float2(cau[2], cau[3]));
            __stcs(c2p + 2, make_float2(cau[4], cau[5]));
        }

        // retire before block exit (smem must stay valid until TMA completes)
        if (lane == 0)
            asm volatile("cp.async.bulk.wait_group 0;" ::: "memory");
    } else {
        // ---- tail / unaligned fallback: scalar path ----
        const int p = block_start + tid;
        if (p >= n) return;
        const float* Fp = F_in + (size_t)p * 9;
        #pragma unroll
        for (int i = 0; i < 9; i++)
            (&F[0][0])[i] = __ldcs(Fp + i);

        nh3d_point(F, c1, c2, psi, cau, dd);

        __stcs(out + p, psi);
        float* cbase = out + (size_t)n + (size_t)p * 6;
        #pragma unroll
        for (int q = 0; q < 6; q++) __stcs(cbase + q, cau[q]);
        float* dbase = out + (size_t)n * 7 + (size_t)p * 36;
        #pragma unroll
        for (int q = 0; q < 36; q++) __stcs(dbase + q, dd[q]);
    }
}

extern "C" void kernel_launch(void* const* d_in, const int* in_sizes, int n_in,
                              void* d_out, int out_size) {
    const float* F_in    = (const float*)d_in[0];
    const float* mat_par = (const float*)d_in[1];
    float* out = (float*)d_out;
    int n = in_sizes[0] / 9;

    // fast path: dd bulk dst (7n floats, 4608B warp chunks) needs 16B,
    // cau float2 needs 8B -> n % 4 == 0.
    int vec_ok = ((n % 4) == 0) ? 1 : 0;

    int blocks = (n + TPB - 1) / TPB;
    nh3d_kernel<<<blocks, TPB>>>(F_in, mat_par, out, n, vec_ok);
}

// round 17
// speedup vs baseline: 1.1006x; 1.0399x over previous
#include <cuda_runtime.h>
#include <cstdint>

// Neo-Hookean 3D material point: psi, Cauchy (Voigt 6), DDSDDE (6x6) per point.
// Output layout (flattened tuple): [N] psi | [N,6] Cauchy6 | [N,36] DDSDDE.
//
// FINAL (== R9 champion, 35.3us): TPB=128, fully warp-local, barrier-free.
// Warp w stages its 32 F's (1152B contiguous LDG.128->STS.128, stride-9
// conflict-free readback), computes the closed-form Neo-Hookean point update
// (B = F F^T collapse of the jacfwd tangent), streams psi/cau out directly
// (.cs, warp-contiguous), stages dd rows in smem (pitch 36 == gmem layout),
// and drains the warp's 4608B chunk with ONE cp.async.bulk S2G.
//
// Measured search summary (16 rounds): coalescing -24.5us, TMA drain -2.5us,
// TPB=128 granularity -1.6us; persistence, L2 policies, occupancy boosts,
// store reordering, 2-tile pipelines all neutral or worse. Steady state runs
// 212MB/replay at ~6.0 TB/s mixed R/W — the practical HBM wall for a write
// stream 1.4x the L2 capacity.

#define TPB 128
#define ROW 36
#define WARPS_PER_BLOCK (TPB / 32)
#define WARP_F_FLOATS  (32 * 9)             // 1152 B per warp
#define WARP_DD_FLOATS (32 * ROW)           // 4608 B per warp
#define DD_SMEM_FLOATS (TPB * ROW)          // 18432 B
#define F_SMEM_FLOATS  (TPB * 9)            //  4608 B

__device__ __forceinline__ uint32_t smem_u32(const void* p) {
    uint32_t a;
    asm("{ .reg .u64 t; cvta.to.shared.u64 t, %1; cvt.u32.u64 %0, t; }"
        : "=r"(a) : "l"(p));
    return a;
}

__device__ __forceinline__ void nh3d_point(
    const float F[3][3], float c1, float c2,
    float& psi, float cau[6], float dd[36])
{
    // B = F F^T (symmetric)
    float B[3][3];
    #pragma unroll
    for (int i = 0; i < 3; i++)
        #pragma unroll
        for (int j = 0; j < 3; j++)
            B[i][j] = F[i][0]*F[j][0] + F[i][1]*F[j][1] + F[i][2]*F[j][2];

    float J = F[0][0]*(F[1][1]*F[2][2] - F[1][2]*F[2][1])
            - F[0][1]*(F[1][0]*F[2][2] - F[1][2]*F[2][0])
            + F[0][2]*(F[1][0]*F[2][1] - F[1][1]*F[2][0]);

    float I1   = B[0][0] + B[1][1] + B[2][2];
    float Jm23 = 1.0f / cbrtf(J * J);      // J^{-2/3}
    float invJ = 1.0f / J;

    float a = 2.0f * c1 * Jm23;
    float b = 2.0f * c2 * (J - 1.0f) * J;

    // Kirchhoff stress tau = a*(B - I1/3 * I) + b*I
    float tau[3][3];
    #pragma unroll
    for (int i = 0; i < 3; i++)
        #pragma unroll
        for (int j = 0; j < 3; j++)
            tau[i][j] = a * (B[i][j] - (i == j ? I1 * (1.0f/3.0f) : 0.0f))
                      + (i == j ? b : 0.0f);

    psi = c1 * (Jm23 * I1 - 3.0f) + c2 * (J - 1.0f) * (J - 1.0f);

    // Spatial tangent (closed-form collapse of einsum('iqks,jq,ls',P_F,F,F)
    // plus geometric correction):
    // Stiff_ijkl = c_dd d_ij d_kl + c_bd (B_ij d_kl + d_ij B_kl)
    //            + a d_ik B_jl + c_sw d_il d_jk
    //            + 0.5*(tau_ik d_jl + tau_il d_jk + tau_jk d_il - tau_jl d_ik)
    float c_dd = (2.0f/9.0f) * a * I1 + 2.0f * c2 * (2.0f*J - 1.0f) * J;
    float c_bd = -(2.0f/3.0f) * a;
    float c_sw = a * I1 * (1.0f/3.0f) - b;

    const int II[6] = {0, 1, 2, 0, 0, 1};
    const int JJ[6] = {0, 1, 2, 1, 2, 2};

    #pragma unroll
    for (int r = 0; r < 6; r++)
        cau[r] = tau[II[r]][JJ[r]] * invJ;

    #pragma unroll
    for (int r = 0; r < 6; r++) {
        const int i = II[r], j = JJ[r];
        #pragma unroll
        for (int c = 0; c < 6; c++) {
            const int k = II[c], l = JJ[c];
            float s = 0.0f;
            if (i == j && k == l) s += c_dd;
            if (k == l)           s += c_bd * B[i][j];
            if (i == j)           s += c_bd * B[k][l];
            if (i == k)           s += a * B[j][l];
            if (i == l && j == k) s += c_sw;
            float g = 0.0f;
            if (j == l) g += tau[i][k];
            if (j == k) g += tau[i][l];
            if (i == l) g += tau[j][k];
            if (i == k) g -= tau[j][l];
            s += 0.5f * g;
            dd[r*6 + c] = s * invJ;
        }
    }
}

__global__ __launch_bounds__(TPB, 9) void nh3d_kernel(
    const float* __restrict__ F_in,
    const float* __restrict__ mat_par,
    float* __restrict__ out,
    int n, int vec_ok)
{
    __shared__ __align__(16) float sdd[DD_SMEM_FLOATS];  // 18432 B
    __shared__ __align__(16) float sf[F_SMEM_FLOATS];    //  4608 B

    const int tid  = threadIdx.x;
    const int wid  = tid >> 5;
    const int lane = tid & 31;
    const int block_start = blockIdx.x * TPB;
    const float c1 = mat_par[0];
    const float c2 = mat_par[1];

    float F[3][3];
    float psi, cau[6], dd[36];

    if (vec_ok && block_start + TPB <= n) {
        const int warp_pt0 = block_start + wid * 32;   // first point of this warp

        // ---- warp-local F staging: 72 float4 (1152B contiguous) per warp ----
        {
            const float4* g4 = reinterpret_cast<const float4*>(F_in + (size_t)warp_pt0 * 9);
            float4* s4 = reinterpret_cast<float4*>(sf + wid * WARP_F_FLOATS);
            s4[lane]      = __ldcs(g4 + lane);
            s4[lane + 32] = __ldcs(g4 + lane + 32);
            if (lane < 8) s4[lane + 64] = __ldcs(g4 + lane + 64);
        }
        __syncwarp();
        {
            const float* myF = sf + wid * WARP_F_FLOATS + lane * 9;  // stride 9: conflict-free
            #pragma unroll
            for (int i = 0; i < 9; i++)
                (&F[0][0])[i] = myF[i];
        }

        nh3d_point(F, c1, c2, psi, cau, dd);

        // ---- psi + cau direct stores first: start the write stream early ----
        {
            const int p = warp_pt0 + lane;
            __stcs(out + p, psi);
            float2* c2p = reinterpret_cast<float2*>(out + (size_t)n + (size_t)p * 6);
            __stcs(c2p + 0, make_float2(cau[0], cau[1]));
            __stcs(c2p + 1, make_float2(cau[2], cau[3]));
            __stcs(c2p + 2, make_float2(cau[4], cau[5]));
        }

        // ---- warp-local dd staging: lane row 144B, warp chunk 4608B ----
        {
            float4* row4 = reinterpret_cast<float4*>(sdd + wid * WARP_DD_FLOATS + lane * ROW);
            #pragma unroll
            for (int q = 0; q < 9; q++)
                row4[q] = make_float4(dd[4*q+0], dd[4*q+1], dd[4*q+2], dd[4*q+3]);
        }
        __syncwarp();

        // lane 0 drains this warp's contiguous chunk with one bulk copy
        if (lane == 0) {
            asm volatile("fence.proxy.async.shared::cta;" ::: "memory");
            float* ddst = out + (size_t)n * 7 + (size_t)warp_pt0 * 36;
            uint32_t src = smem_u32(sdd + wid * WARP_DD_FLOATS);
            asm volatile(
                "cp.async.bulk.global.shared::cta.bulk_group [%0], [%1], %2;"
                :: "l"(ddst), "r"(src), "n"(WARP_DD_FLOATS * 4) : "memory");
            asm volatile("cp.async.bulk.commit_group;" ::: "memory");
            // retire before block exit (smem must stay valid)
            asm volatile("cp.async.bulk.wait_group 0;" ::: "memory");
        }
    } else {
        // ---- tail / unaligned fallback: scalar path ----
        const int p = block_start + tid;
        if (p >= n) return;
        const float* Fp = F_in + (size_t)p * 9;
        #pragma unroll
        for (int i = 0; i < 9; i++)
            (&F[0][0])[i] = __ldcs(Fp + i);

        nh3d_point(F, c1, c2, psi, cau, dd);

        __stcs(out + p, psi);
        float* cbase = out + (size_t)n + (size_t)p * 6;
        #pragma unroll
        for (int q = 0; q < 6; q++) __stcs(cbase + q, cau[q]);
        float* dbase = out + (size_t)n * 7 + (size_t)p * 36;
        #pragma unroll
        for (int q = 0; q < 36; q++) __stcs(dbase + q, dd[q]);
    }
}

extern "C" void kernel_launch(void* const* d_in, const int* in_sizes, int n_in,
                              void* d_out, int out_size) {
    const float* F_in    = (const float*)d_in[0];
    const float* mat_par = (const float*)d_in[1];
    float* out = (float*)d_out;
    int n = in_sizes[0] / 9;

    // fast path: dd bulk dst (7n floats, 4608B warp chunks) needs 16B,
    // cau float2 needs 8B -> n % 4 == 0.
    int vec_ok = ((n % 4) == 0) ? 1 : 0;

    int blocks = (n + TPB - 1) / TPB;
    nh3d_kernel<<<blocks, TPB>>>(F_in, mat_par, out, n, vec_ok);
}